// round 1
// baseline (speedup 1.0000x reference)
#include <cuda_runtime.h>

#define BQ 4
#define LQ 2048
#define DM 64
#define ED 128
#define NQ 32
#define DCV 16
#define DTR 4
#define RQ 68            // DTR + 2*N
#define EPSQ 1e-5f
#define LOG2EF 1.4426950408889634f

// ---------------- scratch (device globals; no allocation allowed) ----------------
__device__ float  g_h[BQ * LQ * DM];          // residual stream        (2 MB)
__device__ float  g_xz[BQ * LQ * 2 * ED];     // in_proj output         (8 MB)
__device__ float4 g_meta[BQ * LQ * ED];       // {delta, delta*xc, silu(z), Dp*xc*silu(z)} (16 MB)
__device__ float2 g_bc[BQ * LQ * NQ];         // {B, C}                 (2 MB)
__device__ float  g_yout[BQ * ED * LQ];       // gated scan output, (B,E,L) layout (4 MB)

// ================= K1: rmsnorm + in_proj =================
// grid: B * (L/32) = 256 blocks, 256 threads. Each block: 32 timesteps.
__global__ void __launch_bounds__(256) k1_rms_inproj(
    const float* __restrict__ hin,
    const float* __restrict__ inw,   // (256, 64)
    const float* __restrict__ inb,   // (256)
    const float* __restrict__ nw)    // (64)
{
    __shared__ float s_nrow[32][68];   // padded rows, float4-aligned (68 % 4 == 0)

    int b  = blockIdx.x >> 6;
    int l0 = (blockIdx.x & 63) << 5;
    int tid = threadIdx.x;
    int lane = tid & 31, wid = tid >> 5;

    // rmsnorm: 8 warps x 4 rows
    #pragma unroll
    for (int il = 0; il < 4; ++il) {
        int l = wid * 4 + il;
        const float* hr = hin + ((size_t)(b * LQ + l0 + l)) * DM;
        float v0 = hr[lane], v1 = hr[lane + 32];
        float ss = v0 * v0 + v1 * v1;
        #pragma unroll
        for (int s = 16; s; s >>= 1) ss += __shfl_xor_sync(~0u, ss, s);
        float r = rsqrtf(ss * (1.0f / DM) + EPSQ);
        s_nrow[l][lane]      = v0 * r * nw[lane];
        s_nrow[l][lane + 32] = v1 * r * nw[lane + 32];
    }
    __syncthreads();

    // in_proj: thread = output channel c (0..255); 32 l positions accumulated in regs
    int c = tid;
    float acc[32];
    #pragma unroll
    for (int l = 0; l < 32; ++l) acc[l] = 0.f;

    const float4* w4p = (const float4*)inw + c * 16;
    #pragma unroll 1
    for (int k4 = 0; k4 < 16; ++k4) {
        float4 w = __ldg(&w4p[k4]);
        #pragma unroll
        for (int l = 0; l < 32; ++l) {
            float4 s = *(const float4*)&s_nrow[l][k4 * 4];
            acc[l] += w.x * s.x + w.y * s.y + w.z * s.z + w.w * s.w;
        }
    }
    float bb = inb[c];
    float* xzp = g_xz + ((size_t)(b * LQ + l0)) * 256 + c;
    #pragma unroll
    for (int l = 0; l < 32; ++l) xzp[(size_t)l * 256] = acc[l] + bb;
}

// ================= K2: causal dwconv + silu + xproj + dtproj + softplus + packing =================
// grid: B * (L/64) = 128 blocks, 256 threads, dynamic smem (buffers aliased in phases).
// smem layout (floats):
//   phase A: s_xin[79*128] @0, s_convw[128*16] @10112         (ends 12160)
//   phase B: s_xw[68*128]  @0, s_dbc[64*69]    @8704          (ends 13120)
//   always : s_xc[64*132]  @13120                             (ends 21568)
#define K2_SMEM_FLOATS 21568
#define K2_SMEM_BYTES  (K2_SMEM_FLOATS * 4)

__global__ void __launch_bounds__(256) k2_conv_xproj(
    const float* __restrict__ convw,   // (128, 16)
    const float* __restrict__ convb,   // (128)
    const float* __restrict__ xprojw,  // (68, 128)
    const float* __restrict__ dtw,     // (128, 4)
    const float* __restrict__ dtb,     // (128)
    const float* __restrict__ Dpw)     // (128)
{
    extern __shared__ float sm[];
    float* s_xin   = sm;
    float* s_convw = sm + 79 * 128;
    float* s_xw    = sm;              // aliases s_xin after conv is done
    float* s_dbc   = sm + 68 * 128;   // 64 rows x 69 (padded)
    float* s_xc    = sm + 13120;      // 64 rows x 132 (padded, float4-aligned)

    int b  = blockIdx.x >> 5;
    int l0 = (blockIdx.x & 31) << 6;
    int tid = threadIdx.x;

    // load conv weights + input halo tile
    for (int i = tid; i < 128 * 16; i += 256) s_convw[i] = convw[i];
    for (int i = tid; i < 79 * 128; i += 256) {
        int r = i >> 7, ch = i & 127;
        int l = l0 - 15 + r;
        s_xin[i] = (l >= 0) ? g_xz[((size_t)(b * LQ + l)) * 256 + ch] : 0.f;
    }
    __syncthreads();

    // causal depthwise conv + silu -> s_xc
    for (int i = tid; i < 64 * 128; i += 256) {
        int l = i >> 7, ch = i & 127;
        float acc = convb[ch];
        #pragma unroll
        for (int j = 0; j < DCV; ++j)
            acc += s_convw[ch * DCV + j] * s_xin[(l + j) * 128 + ch];
        float sg = 1.f / (1.f + __expf(-acc));
        s_xc[l * 132 + ch] = acc * sg;
    }
    __syncthreads();

    // load xproj weights into the (now free) xin region
    for (int i = tid; i < 68 * 128; i += 256) s_xw[i] = xprojw[i];
    __syncthreads();

    // dbc GEMM: out[l][r] = sum_k xc[l][k] * xw[r][k];  thread = (l, r-group of 17)
    {
        int l = tid & 63, rg = tid >> 6;
        float acc[17];
        #pragma unroll
        for (int r = 0; r < 17; ++r) acc[r] = 0.f;
        const float4* xc4 = (const float4*)(s_xc + l * 132);
        #pragma unroll 1
        for (int kc = 0; kc < 4; ++kc) {
            float4 xr[8];
            #pragma unroll
            for (int q = 0; q < 8; ++q) xr[q] = xc4[kc * 8 + q];
            #pragma unroll
            for (int rr = 0; rr < 17; ++rr) {
                const float4* w4 = (const float4*)(s_xw + (rg * 17 + rr) * 128 + kc * 32);
                float a = acc[rr];
                #pragma unroll
                for (int q = 0; q < 8; ++q) {
                    float4 w = w4[q];
                    a += w.x * xr[q].x + w.y * xr[q].y + w.z * xr[q].z + w.w * xr[q].w;
                }
                acc[rr] = a;
            }
        }
        #pragma unroll
        for (int rr = 0; rr < 17; ++rr) s_dbc[l * 69 + rg * 17 + rr] = acc[rr];
    }
    __syncthreads();

    // dtproj + softplus + pack scan operands
    for (int i = tid; i < 64 * 128; i += 256) {
        int l = i >> 7, e = i & 127;
        const float* dr = s_dbc + l * 69;
        float4 wv = *(const float4*)(dtw + e * 4);
        float v = dr[0] * wv.x + dr[1] * wv.y + dr[2] * wv.z + dr[3] * wv.w + dtb[e];
        float delta = (v > 20.f) ? v : log1pf(__expf(v));
        float xcv = s_xc[l * 132 + e];
        float z  = g_xz[((size_t)(b * LQ + l0 + l)) * 256 + 128 + e];
        float gz = z / (1.f + __expf(-z));
        float4 m;
        m.x = delta;
        m.y = delta * xcv;
        m.z = gz;
        m.w = Dpw[e] * xcv * gz;
        g_meta[((size_t)(b * LQ + l0 + l)) * 128 + e] = m;
    }
    // pack (B, C)
    for (int i = tid; i < 64 * 32; i += 256) {
        int l = i >> 5, n = i & 31;
        const float* dr = s_dbc + l * 69;
        g_bc[((size_t)(b * LQ + l0 + l)) * 32 + n] = make_float2(dr[DTR + n], dr[DTR + NQ + n]);
    }
}

// ================= K3: selective scan =================
// grid: 128 blocks x 128 threads = 512 warps; warp = one (b,e) channel, lane = state n.
__global__ void __launch_bounds__(128) k3_scan(const float* __restrict__ Alog)
{
    int g = blockIdx.x * 4 + (threadIdx.x >> 5);
    int lane = threadIdx.x & 31;
    int b = g >> 7, e = g & 127;

    float aA = -__expf(Alog[e * NQ + lane]) * LOG2EF;   // A[e,n] * log2(e)

    const float4* mp = g_meta + (size_t)b * LQ * 128 + e;
    const float2* bp = g_bc   + (size_t)b * LQ * 32 + lane;
    float* yp = g_yout + ((size_t)(b * 128 + e)) * LQ;

    float h = 0.f, ykeep = 0.f;
    for (int t0 = 0; t0 < LQ; t0 += 32) {
        #pragma unroll
        for (int j = 0; j < 32; ++j) {
            float4 m = __ldg(mp + (size_t)(t0 + j) * 128);   // broadcast across lanes
            float2 w = __ldg(bp + (size_t)(t0 + j) * 32);    // coalesced across lanes
            float dA = exp2f(m.x * aA);
            h = fmaf(dA, h, m.y * w.x);
            float yv = h * w.y;
            #pragma unroll
            for (int s = 16; s; s >>= 1) yv += __shfl_xor_sync(~0u, yv, s);
            float yo = fmaf(yv, m.z, m.w);                   // (y)*silu(z) + Dp*xc*silu(z)
            if (j == lane) ykeep = yo;
        }
        yp[t0 + lane] = ykeep;                               // coalesced store of 32 timesteps
    }
}

// ================= K4: out_proj + residual =================
// grid: B * (L/64) = 128 blocks, 256 threads, dynamic smem.
#define K4_SMEM_FLOATS (128 * 64 + 128 * 68)
#define K4_SMEM_BYTES  (K4_SMEM_FLOATS * 4)

__global__ void __launch_bounds__(256) k4_outproj(
    const float* __restrict__ ow,   // (64, 128)
    const float* __restrict__ ob,   // (64)
    const float* __restrict__ hin,
    float* __restrict__ hout)
{
    extern __shared__ float sm4[];
    float* s_y   = sm4;              // [e=128][l=64]
    float* s_owT = sm4 + 128 * 64;   // [k=128][d=64 padded to 68]

    int b  = blockIdx.x >> 5;
    int l0 = (blockIdx.x & 31) << 6;
    int tid = threadIdx.x;

    for (int i = tid; i < 128 * 64; i += 256) {
        int e = i >> 6, lc = i & 63;
        s_y[i] = g_yout[((size_t)(b * 128 + e)) * LQ + l0 + lc];
    }
    for (int i = tid; i < 64 * 128; i += 256) {
        int d = i >> 7, k = i & 127;
        s_owT[k * 68 + d] = ow[i];
    }
    __syncthreads();

    int l = tid & 63, dg = tid >> 6;   // dg: 4 groups of 16 output dims
    float acc[16];
    #pragma unroll
    for (int i = 0; i < 16; ++i) acc[i] = 0.f;

    #pragma unroll 1
    for (int k = 0; k < 128; ++k) {
        float yv = s_y[k * 64 + l];
        const float4* w4 = (const float4*)(s_owT + k * 68 + dg * 16);
        #pragma unroll
        for (int i = 0; i < 4; ++i) {
            float4 w = w4[i];
            acc[4 * i + 0] += yv * w.x;
            acc[4 * i + 1] += yv * w.y;
            acc[4 * i + 2] += yv * w.z;
            acc[4 * i + 3] += yv * w.w;
        }
    }

    size_t base = ((size_t)(b * LQ + l0 + l)) * DM + dg * 16;
    const float4* h4  = (const float4*)(hin + base);
    float4*       o4  = (float4*)(hout + base);
    const float4* ob4 = (const float4*)(ob + dg * 16);
    #pragma unroll
    for (int i = 0; i < 4; ++i) {
        float4 hv = h4[i], bv = ob4[i];
        float4 r;
        r.x = hv.x + bv.x + acc[4 * i + 0];
        r.y = hv.y + bv.y + acc[4 * i + 1];
        r.z = hv.z + bv.z + acc[4 * i + 2];
        r.w = hv.w + bv.w + acc[4 * i + 3];
        o4[i] = r;
    }
}

// ================= final classifier head =================
__global__ void __launch_bounds__(128) k_final(
    const float* __restrict__ fcw, const float* __restrict__ fcb, float* __restrict__ out)
{
    int b = threadIdx.x >> 5, lane = threadIdx.x & 31;
    float s = 0.f;
    #pragma unroll
    for (int j = 0; j < 4; ++j) {
        int e = lane + 32 * j;
        s += g_yout[((size_t)(b * 128 + e)) * LQ + (LQ - 1)] * fcw[e];
    }
    #pragma unroll
    for (int d = 16; d; d >>= 1) s += __shfl_xor_sync(~0u, s, d);
    if (lane == 0) out[b] = s + fcb[0];
}

// ================= launch =================
extern "C" void kernel_launch(void* const* d_in, const int* in_sizes, int n_in,
                              void* d_out, int out_size)
{
    const float* x        = (const float*)d_in[0];
    const float* in_w     = (const float*)d_in[1];
    const float* in_b     = (const float*)d_in[2];
    const float* conv_w   = (const float*)d_in[3];
    const float* conv_b   = (const float*)d_in[4];
    const float* xproj_w  = (const float*)d_in[5];
    const float* dtproj_w = (const float*)d_in[6];
    const float* dtproj_b = (const float*)d_in[7];
    const float* A_log    = (const float*)d_in[8];
    const float* Dp       = (const float*)d_in[9];
    const float* outp_w   = (const float*)d_in[10];
    const float* outp_b   = (const float*)d_in[11];
    const float* norm_w   = (const float*)d_in[12];
    const float* fc_w     = (const float*)d_in[13];
    const float* fc_b     = (const float*)d_in[14];
    float* out = (float*)d_out;

    (void)in_sizes; (void)n_in; (void)out_size;

    // Idempotent attribute sets (not stream ops; legal during graph capture).
    cudaFuncSetAttribute(k2_conv_xproj, cudaFuncAttributeMaxDynamicSharedMemorySize, K2_SMEM_BYTES);
    cudaFuncSetAttribute(k4_outproj,   cudaFuncAttributeMaxDynamicSharedMemorySize, K4_SMEM_BYTES);

    float* gh = nullptr;
    cudaGetSymbolAddress((void**)&gh, g_h);

    for (int i = 0; i < 4; ++i) {
        const float* hin = (i == 0) ? x : gh;
        k1_rms_inproj<<<256, 256>>>(hin,
                                    in_w + (size_t)i * 2 * ED * DM,
                                    in_b + (size_t)i * 2 * ED,
                                    norm_w + (size_t)i * DM);
        k2_conv_xproj<<<128, 256, K2_SMEM_BYTES>>>(
            conv_w   + (size_t)i * ED * DCV,
            conv_b   + (size_t)i * ED,
            xproj_w  + (size_t)i * RQ * ED,
            dtproj_w + (size_t)i * ED * DTR,
            dtproj_b + (size_t)i * ED,
            Dp       + (size_t)i * ED);
        k3_scan<<<128, 128>>>(A_log + (size_t)i * ED * NQ);
        if (i < 3)
            k4_outproj<<<128, 256, K4_SMEM_BYTES>>>(
                outp_w + (size_t)i * DM * ED,
                outp_b + (size_t)i * DM,
                hin, gh);
    }
    k_final<<<1, 128>>>(fc_w, fc_b, out);
}

// round 2
// speedup vs baseline: 2.8413x; 2.8413x over previous
#include <cuda_runtime.h>

#define BQ 4
#define LQ 2048
#define DM 64
#define ED 128
#define NQ 32
#define DCV 16
#define DTR 4
#define RQ 68            // DTR + 2*N
#define EPSQ 1e-5f
#define LOG2EF 1.4426950408889634f

// ---------------- scratch (device globals; no allocation allowed) ----------------
__device__ float  g_h[BQ * LQ * DM];          // residual stream        (2 MB)
__device__ float  g_xz[BQ * LQ * 2 * ED];     // in_proj output         (8 MB)
__device__ float2 g_dx[BQ * LQ * ED];         // {delta, delta*xc}      (8 MB)
__device__ float2 g_gate[BQ * LQ * ED];       // {silu(z), Dp*xc*silu(z)} (8 MB)
__device__ float2 g_bc[BQ * LQ * NQ];         // {B, C}                 (2 MB)
__device__ float  g_yout[BQ * ED * LQ];       // gated scan output, (B,E,L) layout (4 MB)

__device__ __forceinline__ float ex2(float x) {
    float r; asm("ex2.approx.ftz.f32 %0, %1;" : "=f"(r) : "f"(x)); return r;
}

// ================= K1: rmsnorm + in_proj =================
// grid: B * (L/32) = 256 blocks, 256 threads. Each block: 32 timesteps.
__global__ void __launch_bounds__(256) k1_rms_inproj(
    const float* __restrict__ hin,
    const float* __restrict__ inw,   // (256, 64)
    const float* __restrict__ inb,   // (256)
    const float* __restrict__ nw)    // (64)
{
    __shared__ float s_nrow[32][68];   // padded rows, float4-aligned (68 % 4 == 0)

    int b  = blockIdx.x >> 6;
    int l0 = (blockIdx.x & 63) << 5;
    int tid = threadIdx.x;
    int lane = tid & 31, wid = tid >> 5;

    // rmsnorm: 8 warps x 4 rows
    #pragma unroll
    for (int il = 0; il < 4; ++il) {
        int l = wid * 4 + il;
        const float* hr = hin + ((size_t)(b * LQ + l0 + l)) * DM;
        float v0 = hr[lane], v1 = hr[lane + 32];
        float ss = v0 * v0 + v1 * v1;
        #pragma unroll
        for (int s = 16; s; s >>= 1) ss += __shfl_xor_sync(~0u, ss, s);
        float r = rsqrtf(ss * (1.0f / DM) + EPSQ);
        s_nrow[l][lane]      = v0 * r * nw[lane];
        s_nrow[l][lane + 32] = v1 * r * nw[lane + 32];
    }
    __syncthreads();

    // in_proj: thread = output channel c (0..255); 32 l positions accumulated in regs
    int c = tid;
    float acc[32];
    #pragma unroll
    for (int l = 0; l < 32; ++l) acc[l] = 0.f;

    const float4* w4p = (const float4*)inw + c * 16;
    #pragma unroll 1
    for (int k4 = 0; k4 < 16; ++k4) {
        float4 w = __ldg(&w4p[k4]);
        #pragma unroll
        for (int l = 0; l < 32; ++l) {
            float4 s = *(const float4*)&s_nrow[l][k4 * 4];
            acc[l] += w.x * s.x + w.y * s.y + w.z * s.z + w.w * s.w;
        }
    }
    float bb = inb[c];
    float* xzp = g_xz + ((size_t)(b * LQ + l0)) * 256 + c;
    #pragma unroll
    for (int l = 0; l < 32; ++l) xzp[(size_t)l * 256] = acc[l] + bb;
}

// ================= K2: causal dwconv + silu + xproj + dtproj + softplus + packing =================
// grid: B * (L/64) = 128 blocks, 256 threads, dynamic smem (buffers aliased in phases).
#define K2_SMEM_FLOATS 21568
#define K2_SMEM_BYTES  (K2_SMEM_FLOATS * 4)

__global__ void __launch_bounds__(256) k2_conv_xproj(
    const float* __restrict__ convw,   // (128, 16)
    const float* __restrict__ convb,   // (128)
    const float* __restrict__ xprojw,  // (68, 128)
    const float* __restrict__ dtw,     // (128, 4)
    const float* __restrict__ dtb,     // (128)
    const float* __restrict__ Dpw)     // (128)
{
    extern __shared__ float sm[];
    float* s_xin   = sm;
    float* s_convw = sm + 79 * 128;
    float* s_xw    = sm;              // aliases s_xin after conv is done
    float* s_dbc   = sm + 68 * 128;   // 64 rows x 69 (padded)
    float* s_xc    = sm + 13120;      // 64 rows x 132 (padded, float4-aligned)

    int b  = blockIdx.x >> 5;
    int l0 = (blockIdx.x & 31) << 6;
    int tid = threadIdx.x;

    // load conv weights + input halo tile
    for (int i = tid; i < 128 * 16; i += 256) s_convw[i] = convw[i];
    for (int i = tid; i < 79 * 128; i += 256) {
        int r = i >> 7, ch = i & 127;
        int l = l0 - 15 + r;
        s_xin[i] = (l >= 0) ? g_xz[((size_t)(b * LQ + l)) * 256 + ch] : 0.f;
    }
    __syncthreads();

    // causal depthwise conv + silu -> s_xc
    for (int i = tid; i < 64 * 128; i += 256) {
        int l = i >> 7, ch = i & 127;
        float acc = convb[ch];
        #pragma unroll
        for (int j = 0; j < DCV; ++j)
            acc += s_convw[ch * DCV + j] * s_xin[(l + j) * 128 + ch];
        float sg = 1.f / (1.f + __expf(-acc));
        s_xc[l * 132 + ch] = acc * sg;
    }
    __syncthreads();

    // load xproj weights into the (now free) xin region
    for (int i = tid; i < 68 * 128; i += 256) s_xw[i] = xprojw[i];
    __syncthreads();

    // dbc GEMM: out[l][r] = sum_k xc[l][k] * xw[r][k];  thread = (l, r-group of 17)
    {
        int l = tid & 63, rg = tid >> 6;
        float acc[17];
        #pragma unroll
        for (int r = 0; r < 17; ++r) acc[r] = 0.f;
        const float4* xc4 = (const float4*)(s_xc + l * 132);
        #pragma unroll 1
        for (int kc = 0; kc < 4; ++kc) {
            float4 xr[8];
            #pragma unroll
            for (int q = 0; q < 8; ++q) xr[q] = xc4[kc * 8 + q];
            #pragma unroll
            for (int rr = 0; rr < 17; ++rr) {
                const float4* w4 = (const float4*)(s_xw + (rg * 17 + rr) * 128 + kc * 32);
                float a = acc[rr];
                #pragma unroll
                for (int q = 0; q < 8; ++q) {
                    float4 w = w4[q];
                    a += w.x * xr[q].x + w.y * xr[q].y + w.z * xr[q].z + w.w * xr[q].w;
                }
                acc[rr] = a;
            }
        }
        #pragma unroll
        for (int rr = 0; rr < 17; ++rr) s_dbc[l * 69 + rg * 17 + rr] = acc[rr];
    }
    __syncthreads();

    // dtproj + softplus + pack scan operands
    for (int i = tid; i < 64 * 128; i += 256) {
        int l = i >> 7, e = i & 127;
        const float* dr = s_dbc + l * 69;
        float4 wv = *(const float4*)(dtw + e * 4);
        float v = dr[0] * wv.x + dr[1] * wv.y + dr[2] * wv.z + dr[3] * wv.w + dtb[e];
        float delta = (v > 20.f) ? v : log1pf(__expf(v));
        float xcv = s_xc[l * 132 + e];
        float z  = g_xz[((size_t)(b * LQ + l0 + l)) * 256 + 128 + e];
        float gz = z / (1.f + __expf(-z));
        size_t oidx = ((size_t)(b * LQ + l0 + l)) * 128 + e;
        g_dx[oidx]   = make_float2(delta, delta * xcv);
        g_gate[oidx] = make_float2(gz, Dpw[e] * xcv * gz);
    }
    // pack (B, C)
    for (int i = tid; i < 64 * 32; i += 256) {
        int l = i >> 5, n = i & 31;
        const float* dr = s_dbc + l * 69;
        g_bc[((size_t)(b * LQ + l0 + l)) * 32 + n] = make_float2(dr[DTR + n], dr[DTR + NQ + n]);
    }
}

// ================= K3: chunked selective scan =================
// grid: 512 blocks = (b,e); block: 512 threads = 16 warps; warp = chunk of 128 steps;
// lane = state index n. 3-phase linear-recurrence decomposition:
//   p1: local scan from h=0 carrying (h_final, P = prod dA); p2: 16-step cross-chunk
//   combine (warp 0); p3: rescan with true h_start, butterfly-reduce y over n.
__global__ void __launch_bounds__(512) k3_scan(const float* __restrict__ Alog)
{
    __shared__ float s_hf[16][32];
    __shared__ float s_P [16][32];
    __shared__ float s_hs[16][32];

    int b = blockIdx.x >> 7, e = blockIdx.x & 127;
    int lane = threadIdx.x & 31, c = threadIdx.x >> 5;

    float aA = -__expf(Alog[e * NQ + lane]) * LOG2EF;   // A[e,n] * log2(e)

    const float2* dxp = g_dx + ((size_t)(b * LQ) + c * 128) * 128 + e;
    const float2* bcp = g_bc + ((size_t)(b * LQ) + c * 128) * 32 + lane;

    // ---- phase 1: local scan ----
    float h = 0.f, P = 1.f;
    #pragma unroll 8
    for (int j = 0; j < 128; ++j) {
        float2 m = __ldg(dxp + (size_t)j * 128);   // broadcast across lanes
        float2 w = __ldg(bcp + (size_t)j * 32);    // coalesced across lanes
        float dA = ex2(m.x * aA);
        h = fmaf(dA, h, m.y * w.x);
        P *= dA;
    }
    s_hf[c][lane] = h;
    s_P [c][lane] = P;
    __syncthreads();

    // ---- phase 2: cross-chunk exclusive combine (one warp, lane = n) ----
    if (threadIdx.x < 32) {
        float hs = 0.f;
        #pragma unroll
        for (int cc = 0; cc < 16; ++cc) {
            s_hs[cc][lane] = hs;
            hs = fmaf(s_P[cc][lane], hs, s_hf[cc][lane]);
        }
    }
    __syncthreads();

    // ---- phase 3: rescan with true h_start, produce gated y ----
    const float2* gtp = g_gate + ((size_t)(b * LQ) + c * 128) * 128 + e;
    float* yp = g_yout + ((size_t)(b * 128 + e)) * LQ + c * 128;

    h = s_hs[c][lane];
    for (int t0 = 0; t0 < 128; t0 += 32) {
        float ysum = 0.f;
        #pragma unroll
        for (int j = 0; j < 32; ++j) {
            float2 m = __ldg(dxp + (size_t)(t0 + j) * 128);
            float2 w = __ldg(bcp + (size_t)(t0 + j) * 32);
            float dA = ex2(m.x * aA);
            h = fmaf(dA, h, m.y * w.x);
            float yv = h * w.y;
            #pragma unroll
            for (int s = 16; s; s >>= 1) yv += __shfl_xor_sync(~0u, yv, s);
            if (j == lane) ysum = yv;
        }
        float2 g = __ldg(gtp + (size_t)(t0 + lane) * 128);
        yp[t0 + lane] = fmaf(ysum, g.x, g.y);     // y*silu(z) + Dp*xc*silu(z)
    }
}

// ================= K4: out_proj + residual =================
// grid: B * (L/16) = 512 blocks, 256 threads, static smem (~43.5 KB).
__global__ void __launch_bounds__(256) k4_outproj(
    const float* __restrict__ ow,   // (64, 128)
    const float* __restrict__ ob,   // (64)
    const float* __restrict__ hin,
    float* __restrict__ hout)
{
    __shared__ float s_y[128 * 17];   // [e][l], padded
    __shared__ float s_w[128 * 68];   // [k][d], padded (float4-aligned)

    int b  = blockIdx.x >> 7;
    int l0 = (blockIdx.x & 127) << 4;
    int tid = threadIdx.x;

    for (int i = tid; i < 128 * 16; i += 256) {
        int e = i >> 4, lc = i & 15;
        s_y[e * 17 + lc] = g_yout[((size_t)(b * 128 + e)) * LQ + l0 + lc];
    }
    for (int i = tid; i < 64 * 128; i += 256) {
        int d = i >> 7, k = i & 127;
        s_w[k * 68 + d] = ow[i];
    }
    __syncthreads();

    int l = tid & 15, dg = tid >> 4;   // dg: 16 groups of 4 output dims
    float acc0 = 0.f, acc1 = 0.f, acc2 = 0.f, acc3 = 0.f;

    #pragma unroll 4
    for (int k = 0; k < 128; ++k) {
        float yv = s_y[k * 17 + l];
        float4 w = *(const float4*)(s_w + k * 68 + dg * 4);
        acc0 += yv * w.x;
        acc1 += yv * w.y;
        acc2 += yv * w.z;
        acc3 += yv * w.w;
    }

    size_t base = ((size_t)(b * LQ + l0 + l)) * DM + dg * 4;
    float4 hv = *(const float4*)(hin + base);
    float4 bv = *(const float4*)(ob + dg * 4);
    float4 r;
    r.x = hv.x + bv.x + acc0;
    r.y = hv.y + bv.y + acc1;
    r.z = hv.z + bv.z + acc2;
    r.w = hv.w + bv.w + acc3;
    *(float4*)(hout + base) = r;
}

// ================= final classifier head =================
__global__ void __launch_bounds__(128) k_final(
    const float* __restrict__ fcw, const float* __restrict__ fcb, float* __restrict__ out)
{
    int b = threadIdx.x >> 5, lane = threadIdx.x & 31;
    float s = 0.f;
    #pragma unroll
    for (int j = 0; j < 4; ++j) {
        int e = lane + 32 * j;
        s += g_yout[((size_t)(b * 128 + e)) * LQ + (LQ - 1)] * fcw[e];
    }
    #pragma unroll
    for (int d = 16; d; d >>= 1) s += __shfl_xor_sync(~0u, s, d);
    if (lane == 0) out[b] = s + fcb[0];
}

// ================= launch =================
extern "C" void kernel_launch(void* const* d_in, const int* in_sizes, int n_in,
                              void* d_out, int out_size)
{
    const float* x        = (const float*)d_in[0];
    const float* in_w     = (const float*)d_in[1];
    const float* in_b     = (const float*)d_in[2];
    const float* conv_w   = (const float*)d_in[3];
    const float* conv_b   = (const float*)d_in[4];
    const float* xproj_w  = (const float*)d_in[5];
    const float* dtproj_w = (const float*)d_in[6];
    const float* dtproj_b = (const float*)d_in[7];
    const float* A_log    = (const float*)d_in[8];
    const float* Dp       = (const float*)d_in[9];
    const float* outp_w   = (const float*)d_in[10];
    const float* outp_b   = (const float*)d_in[11];
    const float* norm_w   = (const float*)d_in[12];
    const float* fc_w     = (const float*)d_in[13];
    const float* fc_b     = (const float*)d_in[14];
    float* out = (float*)d_out;

    (void)in_sizes; (void)n_in; (void)out_size;

    cudaFuncSetAttribute(k2_conv_xproj, cudaFuncAttributeMaxDynamicSharedMemorySize, K2_SMEM_BYTES);

    float* gh = nullptr;
    cudaGetSymbolAddress((void**)&gh, g_h);

    for (int i = 0; i < 4; ++i) {
        const float* hin = (i == 0) ? x : gh;
        k1_rms_inproj<<<256, 256>>>(hin,
                                    in_w + (size_t)i * 2 * ED * DM,
                                    in_b + (size_t)i * 2 * ED,
                                    norm_w + (size_t)i * DM);
        k2_conv_xproj<<<128, 256, K2_SMEM_BYTES>>>(
            conv_w   + (size_t)i * ED * DCV,
            conv_b   + (size_t)i * ED,
            xproj_w  + (size_t)i * RQ * ED,
            dtproj_w + (size_t)i * ED * DTR,
            dtproj_b + (size_t)i * ED,
            Dp       + (size_t)i * ED);
        k3_scan<<<512, 512>>>(A_log + (size_t)i * ED * NQ);
        if (i < 3)
            k4_outproj<<<512, 256>>>(
                outp_w + (size_t)i * DM * ED,
                outp_b + (size_t)i * DM,
                hin, gh);
    }
    k_final<<<1, 128>>>(fc_w, fc_b, out);
}